// round 10
// baseline (speedup 1.0000x reference)
#include <cuda_runtime.h>

#define B   16
#define KV  8192
#define D   1024
#define D4  256        // D / 4 (float4 per row)
#define NSPLIT 32      // KV splits
#define KPS (KV / NSPLIT)   // 256 keys per split

// ---------------- device scratch ----------------
__device__ float g_q [B * D];
__device__ float g_nk[B * D];
__device__ float g_nv[B * D];
__device__ float g_partial[B * NSPLIT * D];   // 2 MB, unnormalized V partials
__device__ float g_m[B * NSPLIT];             // local maxima
__device__ float g_l[B * NSPLIT];             // local exp-sums

// ---------------- stream/event for fork-join (created once, not device mem) ----
static cudaStream_t g_s2;
static cudaEvent_t  g_ev_fork, g_ev_join;
static struct StreamInit {
    StreamInit() {
        cudaStreamCreateWithFlags(&g_s2, cudaStreamNonBlocking);
        cudaEventCreateWithFlags(&g_ev_fork, cudaEventDisableTiming);
        cudaEventCreateWithFlags(&g_ev_join, cudaEventDisableTiming);
    }
} g_stream_init;

// ---------------- K0a: q projection (wq only) ----------------
// grid (64, 2), block 256 (8 warps). Each warp: 2 rows x 8 batches.
__global__ void q_proj_kernel(const float* __restrict__ x,
                              const float* __restrict__ wq) {
    __shared__ float4 xs[8 * D4];   // 8 batches of x, 32 KB
    const int tid  = threadIdx.x;
    const int warp = tid >> 5;
    const int lane = tid & 31;
    const int grp  = blockIdx.y;

    const float4* x4 = (const float4*)x;
    for (int i = tid; i < 8 * D4; i += 256) xs[i] = x4[grp * 8 * D4 + i];
    __syncthreads();

    const int eA = blockIdx.x * 16 + warp * 2;   // 0..1022 (even)
    const int eB = eA + 1;
    const float4* WA4 = (const float4*)wq + (size_t)eA * D4;
    const float4* WB4 = (const float4*)wq + (size_t)eB * D4;

    float accA[8], accB[8];
#pragma unroll
    for (int b = 0; b < 8; b++) { accA[b] = 0.f; accB[b] = 0.f; }

#pragma unroll
    for (int ii = 0; ii < 8; ii++) {
        const int i = lane + ii * 32;
        const float4 wa = WA4[i];
        const float4 wb = WB4[i];
#pragma unroll
        for (int b = 0; b < 8; b++) {
            const float4 xv = xs[b * D4 + i];
            accA[b] += wa.x * xv.x + wa.y * xv.y + wa.z * xv.z + wa.w * xv.w;
            accB[b] += wb.x * xv.x + wb.y * xv.y + wb.z * xv.z + wb.w * xv.w;
        }
    }
#pragma unroll
    for (int b = 0; b < 8; b++) {
#pragma unroll
        for (int o = 16; o > 0; o >>= 1) {
            accA[b] += __shfl_xor_sync(0xffffffffu, accA[b], o);
            accB[b] += __shfl_xor_sync(0xffffffffu, accB[b], o);
        }
    }
    if (lane == 0) {
#pragma unroll
        for (int b = 0; b < 8; b++) {
            g_q[(grp * 8 + b) * D + eA] = accA[b];
            g_q[(grp * 8 + b) * D + eB] = accB[b];
        }
    }
}

// ---------------- K0b: k/v projections (wk, wv) — runs concurrent with attn ----
// grid (128, 2), block 256 (8 warps). Each warp: 2 rows x 8 batches.
__global__ void kv_proj_kernel(const float* __restrict__ x,
                               const float* __restrict__ wk,
                               const float* __restrict__ wv) {
    __shared__ float4 xs[8 * D4];   // 8 batches of x, 32 KB
    const int tid  = threadIdx.x;
    const int warp = tid >> 5;
    const int lane = tid & 31;
    const int grp  = blockIdx.y;

    const float4* x4 = (const float4*)x;
    for (int i = tid; i < 8 * D4; i += 256) xs[i] = x4[grp * 8 * D4 + i];
    __syncthreads();

    const int rowA = blockIdx.x * 16 + warp * 2;   // 0..2046 (even)
    const int rowB = rowA + 1;
    const int matA = rowA >> 10, eA = rowA & 1023;
    const int matB = rowB >> 10, eB = rowB & 1023;
    const float* WA  = (matA == 0) ? wk   : wv;
    const float* WB  = (matB == 0) ? wk   : wv;
    float*      outA = (matA == 0) ? g_nk : g_nv;
    float*      outB = (matB == 0) ? g_nk : g_nv;
    const float4* WA4 = (const float4*)WA + (size_t)eA * D4;
    const float4* WB4 = (const float4*)WB + (size_t)eB * D4;

    float accA[8], accB[8];
#pragma unroll
    for (int b = 0; b < 8; b++) { accA[b] = 0.f; accB[b] = 0.f; }

#pragma unroll
    for (int ii = 0; ii < 8; ii++) {
        const int i = lane + ii * 32;
        const float4 wa = WA4[i];
        const float4 wb = WB4[i];
#pragma unroll
        for (int b = 0; b < 8; b++) {
            const float4 xv = xs[b * D4 + i];
            accA[b] += wa.x * xv.x + wa.y * xv.y + wa.z * xv.z + wa.w * xv.w;
            accB[b] += wb.x * xv.x + wb.y * xv.y + wb.z * xv.z + wb.w * xv.w;
        }
    }
#pragma unroll
    for (int b = 0; b < 8; b++) {
#pragma unroll
        for (int o = 16; o > 0; o >>= 1) {
            accA[b] += __shfl_xor_sync(0xffffffffu, accA[b], o);
            accB[b] += __shfl_xor_sync(0xffffffffu, accB[b], o);
        }
    }
    if (lane == 0) {
#pragma unroll
        for (int b = 0; b < 8; b++) {
            outA[(grp * 8 + b) * D + eA] = accA[b];
            outB[(grp * 8 + b) * D + eB] = accB[b];
        }
    }
}

// ---------------- K1: fused scores + local softmax + weighted AV partial ----------------
// grid (NSPLIT, B), block 256 (8 warps). Each block: 256 keys of one batch.
__global__ void attn_kernel(const float* __restrict__ cache_k,
                            const float* __restrict__ cache_v) {
    const int split = blockIdx.x;
    const int b     = blockIdx.y;
    const int tid   = threadIdx.x;
    const int warp  = tid >> 5;
    const int lane  = tid & 31;
    const int key0  = split * KPS;

    __shared__ float4 qs[D4];       // 4 KB
    __shared__ float  ss[KPS];      // scores -> exp weights (256)
    __shared__ float  wred[8];

    qs[tid] = ((const float4*)g_q)[b * D4 + tid];
    __syncthreads();

    // ---- phase 1: scores for 256 keys (32 per warp, 2-key ILP) ----
    const float4* K4 = (const float4*)cache_k;
    const int kw0 = warp * 32;
#pragma unroll 1
    for (int j = 0; j < 16; j++) {
        const int kA = kw0 + j;
        const int kB = kA + 16;
        const float4* rowA = K4 + (size_t)(b * KV + key0 + kA) * D4;
        const float4* rowB = K4 + (size_t)(b * KV + key0 + kB) * D4;
        float aA = 0.f, aB = 0.f;
#pragma unroll
        for (int ii = 0; ii < 8; ii++) {
            const int i = lane + ii * 32;
            const float4 qq = qs[i];
            const float4 ka = rowA[i];
            const float4 kb = rowB[i];
            aA += ka.x * qq.x + ka.y * qq.y + ka.z * qq.z + ka.w * qq.w;
            aB += kb.x * qq.x + kb.y * qq.y + kb.z * qq.z + kb.w * qq.w;
        }
#pragma unroll
        for (int o = 16; o > 0; o >>= 1) {
            aA += __shfl_xor_sync(0xffffffffu, aA, o);
            aB += __shfl_xor_sync(0xffffffffu, aB, o);
        }
        if (lane == 0) {
            ss[kA] = aA * 0.03125f;   // 1/sqrt(1024)
            ss[kB] = aB * 0.03125f;
        }
    }
    __syncthreads();

    // ---- local softmax stats: m = max, l = sum exp(s-m); exp stored in ss ----
    float mv = ss[tid];
#pragma unroll
    for (int o = 16; o > 0; o >>= 1)
        mv = fmaxf(mv, __shfl_xor_sync(0xffffffffu, mv, o));
    if (lane == 0) wred[warp] = mv;
    __syncthreads();
    if (tid == 0) {
        float m = wred[0];
#pragma unroll
        for (int w = 1; w < 8; w++) m = fmaxf(m, wred[w]);
        wred[0] = m;
    }
    __syncthreads();
    const float m = wred[0];
    __syncthreads();

    float ev;
    {
        const float e = __expf(ss[tid] - m);
        ss[tid] = e;
        ev = e;
    }
#pragma unroll
    for (int o = 16; o > 0; o >>= 1)
        ev += __shfl_xor_sync(0xffffffffu, ev, o);
    if (lane == 0) wred[warp] = ev;
    __syncthreads();
    if (tid == 0) {
        float l = 0.f;
#pragma unroll
        for (int w = 0; w < 8; w++) l += wred[w];
        g_m[b * NSPLIT + split] = m;
        g_l[b * NSPLIT + split] = l;
    }
    __syncthreads();

    // ---- phase 2: partial = sum_k exp(s_k - m) * v[k][:] ----
    const float4* V4 = (const float4*)cache_v;
    const float4* base = V4 + (size_t)(b * KV + key0) * D4 + tid;
    float4 acc = make_float4(0.f, 0.f, 0.f, 0.f);
#pragma unroll 16
    for (int k = 0; k < KPS; k++) {
        const float  w = ss[k];
        const float4 v = base[(size_t)k * D4];
        acc.x += w * v.x; acc.y += w * v.y;
        acc.z += w * v.z; acc.w += w * v.w;
    }
    ((float4*)g_partial)[(size_t)(b * NSPLIT + split) * D4 + tid] = acc;
}

// ---------------- K2: global rescale + new-token term + round ----------------
// grid B, block 256. One block per batch; each thread owns one float4 column
// and bursts through all 32 splits with high MLP. One barrier total.
__global__ void reduce_kernel(float* __restrict__ out) {
    const int b   = blockIdx.x;
    const int tid = threadIdx.x;   // = float4 column

    __shared__ float wred[8];
    __shared__ float sc[NSPLIT];
    __shared__ float s_wn_sh;

    // ---- parallel new-key score: q . new_k / sqrt(D) ----
    {
        const float4 qq = ((const float4*)g_q )[b * D4 + tid];
        const float4 kk = ((const float4*)g_nk)[b * D4 + tid];
        float p = qq.x * kk.x + qq.y * kk.y + qq.z * kk.z + qq.w * kk.w;
#pragma unroll
        for (int o = 16; o > 0; o >>= 1)
            p += __shfl_xor_sync(0xffffffffu, p, o);
        if ((tid & 31) == 0) wred[tid >> 5] = p;
    }
    __syncthreads();

    // ---- warp 0: combine stats fully in-warp, write weights to smem ----
    if (tid < 32) {
        float sn = (tid < 8) ? wred[tid] : 0.f;
#pragma unroll
        for (int o = 4; o > 0; o >>= 1)
            sn += __shfl_xor_sync(0xffffffffu, sn, o);
        sn = __shfl_sync(0xffffffffu, sn, 0) * 0.03125f;   // s_new

        const float ms = g_m[b * NSPLIT + tid];
        const float ls = g_l[b * NSPLIT + tid];
        float M = fmaxf(ms, sn);
#pragma unroll
        for (int o = 16; o > 0; o >>= 1)
            M = fmaxf(M, __shfl_xor_sync(0xffffffffu, M, o));

        const float e = __expf(ms - M);
        float L = ls * e;
#pragma unroll
        for (int o = 16; o > 0; o >>= 1)
            L += __shfl_xor_sync(0xffffffffu, L, o);
        const float en = __expf(sn - M);
        const float inv = 1.f / (L + en);

        sc[tid] = e * inv;
        if (tid == 0) s_wn_sh = en * inv;
    }
    __syncthreads();

    // ---- burst combine: 32 weighted partials per thread, MLP 8 ----
    const float4* P4 = (const float4*)g_partial + (size_t)b * NSPLIT * D4 + tid;
    float4 a = make_float4(0.f, 0.f, 0.f, 0.f);
#pragma unroll 8
    for (int s = 0; s < NSPLIT; s++) {
        const float  w = sc[s];
        const float4 p = P4[(size_t)s * D4];
        a.x += w * p.x; a.y += w * p.y;
        a.z += w * p.z; a.w += w * p.w;
    }
    const float wn = s_wn_sh;
    const float4 nv = ((const float4*)g_nv)[b * D4 + tid];
    a.x += wn * nv.x; a.y += wn * nv.y;
    a.z += wn * nv.z; a.w += wn * nv.w;

    a.x = rintf(a.x * 10000.f) / 10000.f;
    a.y = rintf(a.y * 10000.f) / 10000.f;
    a.z = rintf(a.z * 10000.f) / 10000.f;
    a.w = rintf(a.w * 10000.f) / 10000.f;
    ((float4*)out)[b * D4 + tid] = a;
}

// ---------------- launcher: fork kv_proj onto side stream, hidden under attn ----
extern "C" void kernel_launch(void* const* d_in, const int* in_sizes, int n_in,
                              void* d_out, int out_size) {
    const float* x  = (const float*)d_in[0];
    const float* ck = (const float*)d_in[1];
    const float* cv = (const float*)d_in[2];
    const float* wq = (const float*)d_in[3];
    const float* wk = (const float*)d_in[4];
    const float* wv = (const float*)d_in[5];
    float* out = (float*)d_out;

    // fork: side stream branches off the main (captured) stream
    cudaEventRecord(g_ev_fork, 0);
    cudaStreamWaitEvent(g_s2, g_ev_fork, 0);

    // side stream: k/v projections (only needed by reduce)
    kv_proj_kernel<<<dim3(128, 2), 256, 0, g_s2>>>(x, wk, wv);
    cudaEventRecord(g_ev_join, g_s2);

    // main stream: q projection, then the big attention pass
    q_proj_kernel<<<dim3(64, 2), 256>>>(x, wq);
    attn_kernel  <<<dim3(NSPLIT, B), 256>>>(ck, cv);

    // join, then final reduce
    cudaStreamWaitEvent(0, g_ev_join, 0);
    reduce_kernel<<<B, 256>>>(out);
}

// round 11
// speedup vs baseline: 1.0221x; 1.0221x over previous
#include <cuda_runtime.h>

#define B   16
#define KV  8192
#define D   1024
#define D4  256        // D / 4 (float4 per row)
#define NSPLIT 32      // KV splits
#define KPS (KV / NSPLIT)   // 256 keys per split
#define KV_BLOCKS 256  // kv_proj grid size

// ---------------- device scratch ----------------
__device__ float g_q [B * D];
__device__ float g_nk[B * D];
__device__ float g_nv[B * D];
__device__ float g_partial[B * NSPLIT * D];   // 2 MB, unnormalized V partials
__device__ float g_m[B * NSPLIT];             // local maxima
__device__ float g_l[B * NSPLIT];             // local exp-sums
__device__ unsigned int g_cnt[B];             // per-batch completion counters
__device__ unsigned int g_kv_cnt;             // kv_proj completion counter
__device__ unsigned int g_fin_cnt;            // combiner completion counter

// ---------------- stream/event for fork (created once, not device mem) ----
static cudaStream_t g_s2;
static cudaEvent_t  g_ev_fork, g_ev_join;
static struct StreamInit {
    StreamInit() {
        cudaStreamCreateWithFlags(&g_s2, cudaStreamNonBlocking);
        cudaEventCreateWithFlags(&g_ev_fork, cudaEventDisableTiming);
        cudaEventCreateWithFlags(&g_ev_join, cudaEventDisableTiming);
    }
} g_stream_init;

// ---------------- K0a: q projection (wq only) ----------------
// grid (64, 2), block 256 (8 warps). Each warp: 2 rows x 8 batches.
__global__ void q_proj_kernel(const float* __restrict__ x,
                              const float* __restrict__ wq) {
    __shared__ float4 xs[8 * D4];   // 8 batches of x, 32 KB
    const int tid  = threadIdx.x;
    const int warp = tid >> 5;
    const int lane = tid & 31;
    const int grp  = blockIdx.y;

    const float4* x4 = (const float4*)x;
    for (int i = tid; i < 8 * D4; i += 256) xs[i] = x4[grp * 8 * D4 + i];
    __syncthreads();

    const int eA = blockIdx.x * 16 + warp * 2;   // 0..1022 (even)
    const int eB = eA + 1;
    const float4* WA4 = (const float4*)wq + (size_t)eA * D4;
    const float4* WB4 = (const float4*)wq + (size_t)eB * D4;

    float accA[8], accB[8];
#pragma unroll
    for (int b = 0; b < 8; b++) { accA[b] = 0.f; accB[b] = 0.f; }

#pragma unroll
    for (int ii = 0; ii < 8; ii++) {
        const int i = lane + ii * 32;
        const float4 wa = WA4[i];
        const float4 wb = WB4[i];
#pragma unroll
        for (int b = 0; b < 8; b++) {
            const float4 xv = xs[b * D4 + i];
            accA[b] += wa.x * xv.x + wa.y * xv.y + wa.z * xv.z + wa.w * xv.w;
            accB[b] += wb.x * xv.x + wb.y * xv.y + wb.z * xv.z + wb.w * xv.w;
        }
    }
#pragma unroll
    for (int b = 0; b < 8; b++) {
#pragma unroll
        for (int o = 16; o > 0; o >>= 1) {
            accA[b] += __shfl_xor_sync(0xffffffffu, accA[b], o);
            accB[b] += __shfl_xor_sync(0xffffffffu, accB[b], o);
        }
    }
    if (lane == 0) {
#pragma unroll
        for (int b = 0; b < 8; b++) {
            g_q[(grp * 8 + b) * D + eA] = accA[b];
            g_q[(grp * 8 + b) * D + eB] = accB[b];
        }
    }
}

// ---------------- K0b: k/v projections — concurrent with attn; signals g_kv_cnt ----
// grid (128, 2), block 256 (8 warps). Each warp: 2 rows x 8 batches.
__global__ void kv_proj_kernel(const float* __restrict__ x,
                               const float* __restrict__ wk,
                               const float* __restrict__ wv) {
    __shared__ float4 xs[8 * D4];   // 8 batches of x, 32 KB
    const int tid  = threadIdx.x;
    const int warp = tid >> 5;
    const int lane = tid & 31;
    const int grp  = blockIdx.y;

    const float4* x4 = (const float4*)x;
    for (int i = tid; i < 8 * D4; i += 256) xs[i] = x4[grp * 8 * D4 + i];
    __syncthreads();

    const int rowA = blockIdx.x * 16 + warp * 2;   // 0..2046 (even)
    const int rowB = rowA + 1;
    const int matA = rowA >> 10, eA = rowA & 1023;
    const int matB = rowB >> 10, eB = rowB & 1023;
    const float* WA  = (matA == 0) ? wk   : wv;
    const float* WB  = (matB == 0) ? wk   : wv;
    float*      outA = (matA == 0) ? g_nk : g_nv;
    float*      outB = (matB == 0) ? g_nk : g_nv;
    const float4* WA4 = (const float4*)WA + (size_t)eA * D4;
    const float4* WB4 = (const float4*)WB + (size_t)eB * D4;

    float accA[8], accB[8];
#pragma unroll
    for (int b = 0; b < 8; b++) { accA[b] = 0.f; accB[b] = 0.f; }

#pragma unroll
    for (int ii = 0; ii < 8; ii++) {
        const int i = lane + ii * 32;
        const float4 wa = WA4[i];
        const float4 wb = WB4[i];
#pragma unroll
        for (int b = 0; b < 8; b++) {
            const float4 xv = xs[b * D4 + i];
            accA[b] += wa.x * xv.x + wa.y * xv.y + wa.z * xv.z + wa.w * xv.w;
            accB[b] += wb.x * xv.x + wb.y * xv.y + wb.z * xv.z + wb.w * xv.w;
        }
    }
#pragma unroll
    for (int b = 0; b < 8; b++) {
#pragma unroll
        for (int o = 16; o > 0; o >>= 1) {
            accA[b] += __shfl_xor_sync(0xffffffffu, accA[b], o);
            accB[b] += __shfl_xor_sync(0xffffffffu, accB[b], o);
        }
    }
    if (lane == 0) {
#pragma unroll
        for (int b = 0; b < 8; b++) {
            outA[(grp * 8 + b) * D + eA] = accA[b];
            outB[(grp * 8 + b) * D + eB] = accB[b];
        }
    }

    // signal completion (release)
    __syncthreads();
    __threadfence();
    if (tid == 0) atomicAdd(&g_kv_cnt, 1u);
}

// ---------------- K1: fused scores + local softmax + AV partial + inline combine ----
// grid (NSPLIT, B), block 256 (8 warps). Each block: 256 keys of one batch.
// The last-finishing block of each batch combines all splits and writes out.
__global__ void attn_kernel(const float* __restrict__ cache_k,
                            const float* __restrict__ cache_v,
                            float* __restrict__ out) {
    const int split = blockIdx.x;
    const int b     = blockIdx.y;
    const int tid   = threadIdx.x;
    const int warp  = tid >> 5;
    const int lane  = tid & 31;
    const int key0  = split * KPS;

    __shared__ float4 qs[D4];       // 4 KB (q, reused by combiner)
    __shared__ float  ss[KPS];      // scores -> exp weights (reused as combine weights)
    __shared__ float  wred[8];
    __shared__ unsigned int s_old;

    qs[tid] = ((const float4*)g_q)[b * D4 + tid];
    __syncthreads();

    // ---- phase 1: scores for 256 keys (32 per warp, 2-key ILP) ----
    const float4* K4 = (const float4*)cache_k;
    const int kw0 = warp * 32;
#pragma unroll 1
    for (int j = 0; j < 16; j++) {
        const int kA = kw0 + j;
        const int kB = kA + 16;
        const float4* rowA = K4 + (size_t)(b * KV + key0 + kA) * D4;
        const float4* rowB = K4 + (size_t)(b * KV + key0 + kB) * D4;
        float aA = 0.f, aB = 0.f;
#pragma unroll
        for (int ii = 0; ii < 8; ii++) {
            const int i = lane + ii * 32;
            const float4 qq = qs[i];
            const float4 ka = rowA[i];
            const float4 kb = rowB[i];
            aA += ka.x * qq.x + ka.y * qq.y + ka.z * qq.z + ka.w * qq.w;
            aB += kb.x * qq.x + kb.y * qq.y + kb.z * qq.z + kb.w * qq.w;
        }
#pragma unroll
        for (int o = 16; o > 0; o >>= 1) {
            aA += __shfl_xor_sync(0xffffffffu, aA, o);
            aB += __shfl_xor_sync(0xffffffffu, aB, o);
        }
        if (lane == 0) {
            ss[kA] = aA * 0.03125f;   // 1/sqrt(1024)
            ss[kB] = aB * 0.03125f;
        }
    }
    __syncthreads();

    // ---- local softmax stats ----
    float mv = ss[tid];
#pragma unroll
    for (int o = 16; o > 0; o >>= 1)
        mv = fmaxf(mv, __shfl_xor_sync(0xffffffffu, mv, o));
    if (lane == 0) wred[warp] = mv;
    __syncthreads();
    if (tid == 0) {
        float m = wred[0];
#pragma unroll
        for (int w = 1; w < 8; w++) m = fmaxf(m, wred[w]);
        wred[0] = m;
    }
    __syncthreads();
    const float m = wred[0];
    __syncthreads();

    float ev;
    {
        const float e = __expf(ss[tid] - m);
        ss[tid] = e;
        ev = e;
    }
#pragma unroll
    for (int o = 16; o > 0; o >>= 1)
        ev += __shfl_xor_sync(0xffffffffu, ev, o);
    if (lane == 0) wred[warp] = ev;
    __syncthreads();
    if (tid == 0) {
        float l = 0.f;
#pragma unroll
        for (int w = 0; w < 8; w++) l += wred[w];
        g_m[b * NSPLIT + split] = m;
        g_l[b * NSPLIT + split] = l;
    }
    __syncthreads();

    // ---- phase 2: partial = sum_k exp(s_k - m) * v[k][:] ----
    const float4* V4 = (const float4*)cache_v;
    const float4* base = V4 + (size_t)(b * KV + key0) * D4 + tid;
    float4 acc = make_float4(0.f, 0.f, 0.f, 0.f);
#pragma unroll 16
    for (int k = 0; k < KPS; k++) {
        const float  w = ss[k];
        const float4 v = base[(size_t)k * D4];
        acc.x += w * v.x; acc.y += w * v.y;
        acc.z += w * v.z; acc.w += w * v.w;
    }
    ((float4*)g_partial)[(size_t)(b * NSPLIT + split) * D4 + tid] = acc;

    // ---- completion handshake: last block of this batch combines ----
    __threadfence();
    __syncthreads();
    if (tid == 0) s_old = atomicAdd(&g_cnt[b], 1u);
    __syncthreads();
    if (s_old != NSPLIT - 1) return;

    // ======== combiner path (one block per batch) ========
    if (tid == 0) {
        g_cnt[b] = 0;   // reset for next graph replay (all adders already done)
        // wait for kv_proj (finishes ~10us into attn's ~165us; effectively no wait)
        while (*(volatile unsigned int*)&g_kv_cnt < KV_BLOCKS) { }
    }
    __syncthreads();
    __threadfence();

    // s_new = q . new_k / sqrt(D)   (q already in qs)
    {
        const float4 qq = qs[tid];
        const float4 kk = __ldcg((const float4*)g_nk + b * D4 + tid);
        float p = qq.x * kk.x + qq.y * kk.y + qq.z * kk.z + qq.w * kk.w;
#pragma unroll
        for (int o = 16; o > 0; o >>= 1)
            p += __shfl_xor_sync(0xffffffffu, p, o);
        if (lane == 0) wred[warp] = p;
    }
    __syncthreads();

    // warp 0: merge stats, write normalized weights into ss[0..NSPLIT], wn in ss[NSPLIT]
    if (tid < 32) {
        float sn = (tid < 8) ? wred[tid] : 0.f;
#pragma unroll
        for (int o = 4; o > 0; o >>= 1)
            sn += __shfl_xor_sync(0xffffffffu, sn, o);
        sn = __shfl_sync(0xffffffffu, sn, 0) * 0.03125f;

        const float ms = g_m[b * NSPLIT + tid];
        const float ls = g_l[b * NSPLIT + tid];
        float M = fmaxf(ms, sn);
#pragma unroll
        for (int o = 16; o > 0; o >>= 1)
            M = fmaxf(M, __shfl_xor_sync(0xffffffffu, M, o));

        const float e = __expf(ms - M);
        float L = ls * e;
#pragma unroll
        for (int o = 16; o > 0; o >>= 1)
            L += __shfl_xor_sync(0xffffffffu, L, o);
        const float en = __expf(sn - M);
        const float inv = 1.f / (L + en);

        ss[tid] = e * inv;
        if (tid == 0) ss[NSPLIT] = en * inv;
    }
    __syncthreads();

    // burst combine: 32 weighted partials per thread (L2-hot), MLP 8
    const float4* P4 = (const float4*)g_partial + (size_t)b * NSPLIT * D4 + tid;
    float4 a = make_float4(0.f, 0.f, 0.f, 0.f);
#pragma unroll 8
    for (int s = 0; s < NSPLIT; s++) {
        const float  w = ss[s];
        const float4 p = P4[(size_t)s * D4];
        a.x += w * p.x; a.y += w * p.y;
        a.z += w * p.z; a.w += w * p.w;
    }
    const float wn = ss[NSPLIT];
    const float4 nv = __ldcg((const float4*)g_nv + b * D4 + tid);
    a.x += wn * nv.x; a.y += wn * nv.y;
    a.z += wn * nv.z; a.w += wn * nv.w;

    a.x = rintf(a.x * 10000.f) / 10000.f;
    a.y = rintf(a.y * 10000.f) / 10000.f;
    a.z = rintf(a.z * 10000.f) / 10000.f;
    a.w = rintf(a.w * 10000.f) / 10000.f;
    ((float4*)out)[b * D4 + tid] = a;

    // last combiner resets the shared counters for the next replay
    __syncthreads();
    if (tid == 0) {
        const unsigned int f = atomicAdd(&g_fin_cnt, 1u);
        if (f == B - 1) {
            g_kv_cnt  = 0;
            g_fin_cnt = 0;
        }
    }
}

// ---------------- launcher: kv_proj forked; attn combines + writes out ----------------
extern "C" void kernel_launch(void* const* d_in, const int* in_sizes, int n_in,
                              void* d_out, int out_size) {
    const float* x  = (const float*)d_in[0];
    const float* ck = (const float*)d_in[1];
    const float* cv = (const float*)d_in[2];
    const float* wq = (const float*)d_in[3];
    const float* wk = (const float*)d_in[4];
    const float* wv = (const float*)d_in[5];
    float* out = (float*)d_out;

    // fork: side stream branches off the main (captured) stream
    cudaEventRecord(g_ev_fork, 0);
    cudaStreamWaitEvent(g_s2, g_ev_fork, 0);

    // side stream: k/v projections (consumed by attn's combiner via device flag)
    kv_proj_kernel<<<dim3(128, 2), 256, 0, g_s2>>>(x, wk, wv);
    cudaEventRecord(g_ev_join, g_s2);

    // main stream: q projection, then fused attention + combine
    q_proj_kernel<<<dim3(64, 2), 256>>>(x, wq);
    attn_kernel  <<<dim3(NSPLIT, B), 256>>>(ck, cv, out);

    // keep the graph well-formed: main stream joins the side stream at the end
    cudaStreamWaitEvent(0, g_ev_join, 0);
}